// round 17
// baseline (speedup 1.0000x reference)
#include <cuda_runtime.h>
#include <cuda_bf16.h>

#define NB 16384
#define ND 512
#define NK 8192
#define BM 64
#define BN 128
#define NPART 8
#define PCOLS (NK / NPART)      // 1024 cols per CTA
#define NTL (PCOLS / BN)        // 8 local n-tiles
#define NSTG (NTL * 8)          // 64 stages (k64 chunks)
#define CAPL 16
#define MARGIN 8.0f
#define APITCH 520              // bf16/row A (1040B) -> conflict-free ldmatrix
#define BPITCH 72               // bf16/row B (144B)  -> conflict-free ldmatrix
#define A_BYTES (BM * APITCH * 2)            // 66560
#define B_OFF   A_BYTES
#define B_STG   (BN * BPITCH * 2)            // 18432
#define ZNL_OFF (B_OFF + 2 * B_STG)          // 103424
#define SBST_OFF (ZNL_OFF + BM * 4)
#define SCNT_OFF (SBST_OFF + BM * 4)
#define CAND_OFF (SCNT_OFF + BM * 4)
#define SMEM_SZ  (CAND_OFF + BM * CAPL * 4)  // 108288 -> 2 CTAs/SM

__device__ float g_enorm[NK];
__device__ float g_znorm[NB];
__device__ unsigned long long g_best[NB];    // (dist_bits<<32)|idx, atomicMin-merged
__device__ float g_lpart[NB / 4];
__device__ __nv_bfloat16 g_zbf[(size_t)NB * ND];
__device__ __nv_bfloat16 g_ebf[(size_t)NK * ND];

__device__ __forceinline__ unsigned sptr(const void* p) {
    unsigned r;
    asm("{ .reg .u64 t; cvta.to.shared.u64 t, %1; cvt.u32.u64 %0, t; }" : "=r"(r) : "l"(p));
    return r;
}
__device__ __forceinline__ void cpa16(unsigned d, const void* s) {
    asm volatile("cp.async.cg.shared.global [%0], [%1], 16;" :: "r"(d), "l"(s));
}
__device__ __forceinline__ void ldm4(unsigned* r, unsigned a) {
    asm volatile("ldmatrix.sync.aligned.m8n8.x4.shared.b16 {%0,%1,%2,%3}, [%4];"
                 : "=r"(r[0]), "=r"(r[1]), "=r"(r[2]), "=r"(r[3]) : "r"(a));
}
__device__ __forceinline__ void mma(float* c, const unsigned* a, unsigned b0, unsigned b1) {
    asm volatile("mma.sync.aligned.m16n8k16.row.col.f32.bf16.bf16.f32 "
                 "{%0,%1,%2,%3}, {%4,%5,%6,%7}, {%8,%9}, {%0,%1,%2,%3};"
                 : "+f"(c[0]), "+f"(c[1]), "+f"(c[2]), "+f"(c[3])
                 : "r"(a[0]), "r"(a[1]), "r"(a[2]), "r"(a[3]), "r"(b0), "r"(b1));
}

// ---- kernel 0: reset merge targets (graph-replay safe) ----
__global__ void init_kernel() {
    int i = blockIdx.x * 1024 + threadIdx.x;
    g_best[i] = ~0ull;
}

// ---- kernel 1: fp32 norms + bf16 convert (warp per row) ----
template <int DST>  // 0: embedding, 1: z
__global__ void prep_kernel(const float* __restrict__ x) {
    int row = blockIdx.x * 4 + (threadIdx.x >> 5), lane = threadIdx.x & 31;
    const float4* p = (const float4*)(x + (size_t)row * ND);
    uint2* bp = (DST == 0 ? (uint2*)g_ebf : (uint2*)g_zbf) + (size_t)row * (ND / 4);
    float s = 0.f;
#pragma unroll
    for (int i = 0; i < 4; ++i) {
        float4 v = p[lane + 32 * i];
        s += v.x * v.x + v.y * v.y + v.z * v.z + v.w * v.w;
        __nv_bfloat162 h0 = __floats2bfloat162_rn(v.x, v.y);
        __nv_bfloat162 h1 = __floats2bfloat162_rn(v.z, v.w);
        uint2 u = { *(unsigned*)&h0, *(unsigned*)&h1 };
        bp[lane + 32 * i] = u;
    }
#pragma unroll
    for (int o = 16; o > 0; o >>= 1) s += __shfl_xor_sync(~0u, s, o);
    if (lane == 0) { if (DST == 0) g_enorm[row] = s; else g_znorm[row] = s; }
}

// B stage: 128 rows x 64 bf16; 256 threads, row = tid/2, 4x16B chunks each
__device__ __forceinline__ void load_bstage(unsigned bb, int c0, int stage, int tid) {
    const int tile = stage >> 3, kb = (stage & 7) * 64;
    const int r = tid >> 1, h = tid & 1;
    const char* src = (const char*)g_ebf + (((size_t)(c0 + tile * BN + r)) * ND + kb + h * 32) * 2;
    unsigned dst = bb + (unsigned)(r * BPITCH + h * 32) * 2;
#pragma unroll
    for (int j = 0; j < 4; ++j) cpa16(dst + j * 16, src + j * 16);
}

// ---- kernel 2: bf16 HMMA filter over 1/8 codebook + exact local rescore + u64 merge ----
__global__ __launch_bounds__(256, 2)
void filter_kernel(const float* __restrict__ zF, const float* __restrict__ eF) {
    extern __shared__ char sm[];
    float* znl  = (float*)(sm + ZNL_OFF);
    int*   sbst = (int*)(sm + SBST_OFF);
    int*   scnt = (int*)(sm + SCNT_OFF);
    int*   cand = (int*)(sm + CAND_OFF);
    const int tid = threadIdx.x, wid = tid >> 5, lane = tid & 31;
    const int bm0 = blockIdx.x * BM;
    const int c0  = blockIdx.y * PCOLS;
    const int wm0 = (wid >> 2) * 32;     // warp m-origin (0 or 32)
    const int wn0 = (wid & 3) * 32;      // warp n-origin within BN tile
    const int g = lane >> 2, t2 = (lane & 3) * 2;
    const unsigned sA = sptr(sm), sB = sA + B_OFF;

    // resident A (64 rows x 512 bf16) + B stage 0
    {
        const char* src = (const char*)g_zbf + (size_t)bm0 * ND * 2;
#pragma unroll
        for (int i = 0; i < 16; ++i) {
            int c = tid + 256 * i, r = c >> 6, o = c & 63;
            cpa16(sA + (unsigned)(r * APITCH + o * 8) * 2, src + (size_t)r * ND * 2 + o * 16);
        }
        load_bstage(sB, c0, 0, tid);
        asm volatile("cp.async.commit_group;");
    }
    for (int i = tid; i < BM; i += 256) {
        sbst[i] = 0x7f7fffff; scnt[i] = 0; znl[i] = g_znorm[bm0 + i];
    }

    float acc[2][4][4];
#pragma unroll
    for (int a = 0; a < 2; ++a)
#pragma unroll
        for (int b = 0; b < 4; ++b)
#pragma unroll
            for (int c = 0; c < 4; ++c) acc[a][b][c] = 0.f;

    for (int s = 0; s < NSTG; ++s) {
        asm volatile("cp.async.wait_group 0;");
        __syncthreads();
        if (s + 1 < NSTG) {
            load_bstage(sB + (unsigned)(((s + 1) & 1) * B_STG), c0, s + 1, tid);
            asm volatile("cp.async.commit_group;");
        }
        const unsigned bb = sB + (unsigned)((s & 1) * B_STG);
        const int ksg = s & 7, n0 = (s >> 3) * BN;

#pragma unroll
        for (int ku = 0; ku < 4; ++ku) {           // 4 k16 steps per stage
            const int ks = ksg * 4 + ku;
            unsigned a0[4], a1[4], b0[4], b1[4];
            ldm4(a0, sA + (unsigned)((wm0      + (lane & 15)) * APITCH + ks * 16 + (lane >> 4) * 8) * 2);
            ldm4(a1, sA + (unsigned)((wm0 + 16 + (lane & 15)) * APITCH + ks * 16 + (lane >> 4) * 8) * 2);
            ldm4(b0, bb + (unsigned)((wn0      + (lane & 15)) * BPITCH + ku * 16 + (lane >> 4) * 8) * 2);
            ldm4(b1, bb + (unsigned)((wn0 + 16 + (lane & 15)) * BPITCH + ku * 16 + (lane >> 4) * 8) * 2);
            // b pairing (validated): same n-octet, both k-halves
            mma(acc[0][0], a0, b0[0], b0[2]); mma(acc[0][1], a0, b0[1], b0[3]);
            mma(acc[0][2], a0, b1[0], b1[2]); mma(acc[0][3], a0, b1[1], b1[3]);
            mma(acc[1][0], a1, b0[0], b0[2]); mma(acc[1][1], a1, b0[1], b0[3]);
            mma(acc[1][2], a1, b1[0], b1[2]); mma(acc[1][3], a1, b1[1], b1[3]);
        }

        if (ksg == 7) {                            // tile epilogue
            float d[2][4][4];
#pragma unroll
            for (int mi = 0; mi < 2; ++mi) {
                int r0 = wm0 + mi * 16 + g;
                float zA = znl[r0], zB = znl[r0 + 8];
                float m0 = 3.4e38f, m1 = 3.4e38f;
#pragma unroll
                for (int ni = 0; ni < 4; ++ni) {
                    int c = c0 + n0 + wn0 + ni * 8 + t2;
                    float e0 = __ldg(&g_enorm[c]), e1 = __ldg(&g_enorm[c + 1]);
                    d[mi][ni][0] = (zA - 2.f * acc[mi][ni][0]) + e0;
                    d[mi][ni][1] = (zA - 2.f * acc[mi][ni][1]) + e1;
                    d[mi][ni][2] = (zB - 2.f * acc[mi][ni][2]) + e0;
                    d[mi][ni][3] = (zB - 2.f * acc[mi][ni][3]) + e1;
                    m0 = fminf(m0, fminf(d[mi][ni][0], d[mi][ni][1]));
                    m1 = fminf(m1, fminf(d[mi][ni][2], d[mi][ni][3]));
                    acc[mi][ni][0] = acc[mi][ni][1] = acc[mi][ni][2] = acc[mi][ni][3] = 0.f;
                }
                atomicMin(&sbst[r0],     __float_as_int(m0));  // positive floats: int order ok
                atomicMin(&sbst[r0 + 8], __float_as_int(m1));
            }
            __syncthreads();
            // local_approx_min >= d(local j*) - 2.6; d~(j*) <= d(j*) + 2.6 < thr:
            // the part's exact argmin is always collected.
#pragma unroll
            for (int mi = 0; mi < 2; ++mi) {
                int r0 = wm0 + mi * 16 + g;
                float t0 = __int_as_float(sbst[r0]) + MARGIN;
                float t1 = __int_as_float(sbst[r0 + 8]) + MARGIN;
#pragma unroll
                for (int ni = 0; ni < 4; ++ni) {
                    int c = c0 + n0 + wn0 + ni * 8 + t2;
#pragma unroll
                    for (int q = 0; q < 4; ++q) {
                        int  rr  = (q < 2) ? r0 : r0 + 8;
                        float th = (q < 2) ? t0 : t1;
                        if (d[mi][ni][q] < th) {
                            int sl = atomicAdd(&scnt[rr], 1);
                            if (sl < CAPL) cand[rr * CAPL + sl] = c + (q & 1);
                        }
                    }
                }
            }
        }
    }

    __syncthreads();
    // ---- exact fp32 rescore of local candidates + packed u64 merge ----
    for (int rr = 0; rr < 8; ++rr) {
        const int lr = wid * 8 + rr, row = bm0 + lr;
        const float4* zp = (const float4*)(zF + (size_t)row * ND);
        float4 zr[4];
#pragma unroll
        for (int i = 0; i < 4; ++i) zr[i] = zp[lane + 32 * i];
        const float zn = g_znorm[row];
        float best = 3.4e38f; int bix = c0;
        const int cnt = scnt[lr];
        const bool ovf = cnt > CAPL;         // safety fallback: full local-part scan
        const int nc = ovf ? PCOLS : cnt;
        for (int k = 0; k < nc; ++k) {
            int ci = ovf ? (c0 + k) : cand[lr * CAPL + k];
            const float4* ep = (const float4*)(eF + (size_t)ci * ND);
            float sd = 0.f;
#pragma unroll
            for (int i = 0; i < 4; ++i) {
                float4 v = ep[lane + 32 * i];
                sd += zr[i].x * v.x + zr[i].y * v.y + zr[i].z * v.z + zr[i].w * v.w;
            }
#pragma unroll
            for (int o = 16; o > 0; o >>= 1) sd += __shfl_xor_sync(~0u, sd, o);
            float dv = (zn - 2.f * sd) + g_enorm[ci];
            if (dv < best || (dv == best && ci < bix)) { best = dv; bix = ci; }
        }
        if (lane == 0) {
            unsigned long long pk =
                ((unsigned long long)__float_as_uint(best) << 32) | (unsigned)bix;
            atomicMin(&g_best[row], pk);     // dist>0: bit order == float order; tie->low idx
        }
    }
}

// ---- kernel 3: gather + indices out + loss partials ----
__global__ void gather_loss_kernel(const float* __restrict__ z, const float* __restrict__ e,
                                   float* __restrict__ outq, float* __restrict__ outidx) {
    int row = blockIdx.x * 4 + (threadIdx.x >> 6), lane = threadIdx.x & 63;
    int idx = (int)(g_best[row] & 0xffffffffull);
    if (lane == 0) outidx[row] = (float)idx;
    const float4* zp = (const float4*)(z + (size_t)row * ND);
    const float4* ep = (const float4*)(e + (size_t)idx * ND);
    float4* op = (float4*)(outq + (size_t)row * ND);
    float s = 0.f;
#pragma unroll
    for (int i = 0; i < 2; ++i) {
        float4 a = zp[lane + 64 * i], b = ep[lane + 64 * i];
        op[lane + 64 * i] = b;
        float dx = a.x - b.x, dy = a.y - b.y, dz = a.z - b.z, dw = a.w - b.w;
        s += dx * dx + dy * dy + dz * dz + dw * dw;
    }
#pragma unroll
    for (int o = 16; o > 0; o >>= 1) s += __shfl_xor_sync(~0u, s, o);
    __shared__ float ws[8];
    if ((threadIdx.x & 31) == 0) ws[threadIdx.x >> 5] = s;
    __syncthreads();
    if (threadIdx.x == 0) {
        float ts = 0.f;
#pragma unroll
        for (int i = 0; i < 8; ++i) ts += ws[i];
        g_lpart[blockIdx.x] = ts;
    }
}

// ---- kernel 4: deterministic final loss ----
__global__ void loss_kernel(float* __restrict__ out_loss) {
    __shared__ double red[256];
    double s = 0.0;
    for (int i = threadIdx.x; i < NB / 4; i += 256) s += (double)g_lpart[i];
    red[threadIdx.x] = s;
    __syncthreads();
    for (int o = 128; o > 0; o >>= 1) {
        if (threadIdx.x < o) red[threadIdx.x] += red[threadIdx.x + o];
        __syncthreads();
    }
    if (threadIdx.x == 0)
        out_loss[0] = (float)(0.25 * red[0] / (double)((long long)NB * ND));
}

extern "C" void kernel_launch(void* const* d_in, const int* in_sizes, int n_in,
                              void* d_out, int out_size) {
    const float* z = (const float*)d_in[0];
    const float* e = (const float*)d_in[1];
    float* out     = (float*)d_out;
    float* outidx  = out + (size_t)NB * ND;
    float* outloss = out + (size_t)NB * ND + NB;

    cudaFuncSetAttribute(filter_kernel, cudaFuncAttributeMaxDynamicSharedMemorySize, SMEM_SZ);

    init_kernel<<<NB / 1024, 1024>>>();
    prep_kernel<0><<<NK / 4, 128>>>(e);
    prep_kernel<1><<<NB / 4, 128>>>(z);
    filter_kernel<<<dim3(NB / BM, NPART), 256, SMEM_SZ>>>(z, e);
    gather_loss_kernel<<<NB / 4, 256>>>(z, e, out, outidx);
    loss_kernel<<<1, 256>>>(outloss);
}